// round 14
// baseline (speedup 1.0000x reference)
#include <cuda_runtime.h>
#include <cuda_bf16.h>
#include <math.h>

typedef unsigned long long u64;

// Problem constants (fixed by the dataset)
#define BB 2
#define HH 12
#define SS 3456
#define DD 32
#define FPT 216           // feats per timestep
#define NT (SS / FPT)     // 16 timesteps
#define WIN 8
#define IMG_START 20      // FPT - img_feat_size(196)
#define JOINT_START 4     // IMG_START - act_size(16)
#define NPAST 19          // valid past kv_m: {0,1,2,3,5..19}
#define MAXPAST ((WIN - 1) * NPAST)   // 133
#define NIMG (FPT - IMG_START)        // 196

// scale * log2(e): ex2.approx(dot) == exp(dot/sqrt(32))
#define SCL2E (0.17677669529663689f * 1.4426950408889634f)

// scratch: per tile (b,h,t) x 20 head queries x 36 floats, two regions:
// scr1 = A-role partial (same-t 0..19 + past), scr2 = B-role partial (img keys)
#define SCR_STRIDE 36
#define SCR_TILES (BB * HH * NT)
__device__ float g_scr1[SCR_TILES * 20 * SCR_STRIDE];
__device__ float g_scr2[SCR_TILES * 20 * SCR_STRIDE];

__device__ __forceinline__ u64 fma2(u64 a, u64 b, u64 c) {
    u64 d; asm("fma.rn.f32x2 %0, %1, %2, %3;" : "=l"(d) : "l"(a), "l"(b), "l"(c)); return d;
}
__device__ __forceinline__ u64 pack2(float lo, float hi) {
    u64 d; asm("mov.b64 %0, {%1, %2};" : "=l"(d) : "f"(lo), "f"(hi)); return d;
}
__device__ __forceinline__ void unpack2(u64 a, float& lo, float& hi) {
    asm("mov.b64 {%0, %1}, %2;" : "=f"(lo), "=f"(hi) : "l"(a));
}
__device__ __forceinline__ float ex2(float x) {
    float r; asm("ex2.approx.f32 %0, %1;" : "=f"(r) : "f"(x)); return r;
}

// one key step: dot(q,k) via f32x2, exp, accumulate p*v. K/V rows from smem.
__device__ __forceinline__ void keyStep(const u64* __restrict__ q2, u64* __restrict__ acc,
                                        float& lsum, const float* krow, const float* vrow)
{
    const ulonglong2* k2 = (const ulonglong2*)krow;
    u64 sA = 0ull, sB = 0ull, sC = 0ull, sD = 0ull;
    ulonglong2 kk;
    kk = k2[0]; sA = fma2(q2[0],  kk.x, sA); sB = fma2(q2[1],  kk.y, sB);
    kk = k2[1]; sC = fma2(q2[2],  kk.x, sC); sD = fma2(q2[3],  kk.y, sD);
    kk = k2[2]; sA = fma2(q2[4],  kk.x, sA); sB = fma2(q2[5],  kk.y, sB);
    kk = k2[3]; sC = fma2(q2[6],  kk.x, sC); sD = fma2(q2[7],  kk.y, sD);
    kk = k2[4]; sA = fma2(q2[8],  kk.x, sA); sB = fma2(q2[9],  kk.y, sB);
    kk = k2[5]; sC = fma2(q2[10], kk.x, sC); sD = fma2(q2[11], kk.y, sD);
    kk = k2[6]; sA = fma2(q2[12], kk.x, sA); sB = fma2(q2[13], kk.y, sB);
    kk = k2[7]; sC = fma2(q2[14], kk.x, sC); sD = fma2(q2[15], kk.y, sD);
    const u64 one2 = pack2(1.0f, 1.0f);
    u64 sAB = fma2(sA, one2, sB);
    u64 sCD = fma2(sC, one2, sD);
    u64 sT  = fma2(sAB, one2, sCD);
    float lo, hi; unpack2(sT, lo, hi);
    const float p = ex2(lo + hi);
    lsum += p;
    const u64 p2 = pack2(p, p);
    const ulonglong2* v2 = (const ulonglong2*)vrow;
    ulonglong2 vv;
    vv = v2[0]; acc[0]  = fma2(p2, vv.x, acc[0]);  acc[1]  = fma2(p2, vv.y, acc[1]);
    vv = v2[1]; acc[2]  = fma2(p2, vv.x, acc[2]);  acc[3]  = fma2(p2, vv.y, acc[3]);
    vv = v2[2]; acc[4]  = fma2(p2, vv.x, acc[4]);  acc[5]  = fma2(p2, vv.y, acc[5]);
    vv = v2[3]; acc[6]  = fma2(p2, vv.x, acc[6]);  acc[7]  = fma2(p2, vv.y, acc[7]);
    vv = v2[4]; acc[8]  = fma2(p2, vv.x, acc[8]);  acc[9]  = fma2(p2, vv.y, acc[9]);
    vv = v2[5]; acc[10] = fma2(p2, vv.x, acc[10]); acc[11] = fma2(p2, vv.y, acc[11]);
    vv = v2[6]; acc[12] = fma2(p2, vv.x, acc[12]); acc[13] = fma2(p2, vv.y, acc[13]);
    vv = v2[7]; acc[14] = fma2(p2, vv.x, acc[14]); acc[15] = fma2(p2, vv.y, acc[15]);
}

__device__ __forceinline__ void loadQ(const float* qrowp, u64* q2)
{
    const float4* qg4 = (const float4*)qrowp;
    #pragma unroll
    for (int i = 0; i < 8; i++) {
        float4 x = qg4[i];
        q2[2 * i]     = pack2(x.x * SCL2E, x.y * SCL2E);
        q2[2 * i + 1] = pack2(x.z * SCL2E, x.w * SCL2E);
    }
}

// ============================================================================
// Combined main kernel.  grid.x = 2*NT: t = bx>>1, role = bx&1.
// role 0 (A): 39KB tile (same-t 0..19 + past, JOINT-FIRST); img queries ->
//             out, head-query partials -> g_scr1.
// role 1 (B): stage 196 same-t img K/V rows at pitch 36; 7 warps x 3 passes
//             compute head-query x img-key partials -> g_scr2.
// Parity interleave co-schedules both roles on every SM: B's latency hides
// in A's issue gaps.
// ============================================================================
#define THREADS 224
// A layout (floats)
#define A_SK 0
#define A_SV (IMG_START * DD)                       // 640
#define A_PK (2 * IMG_START * DD)                   // 1280
#define A_PV (2 * IMG_START * DD + MAXPAST * DD)    // 5536
// B layout (floats)
#define B_PITCH 36
#define B_SK 0
#define B_SV (NIMG * B_PITCH)                       // 7056
#define SMEM_BYTES (2 * NIMG * B_PITCH * 4)         // 56448 (max of roles)

__global__ void __launch_bounds__(THREADS, 3)
eye_attn_main(const float* __restrict__ q,
              const float* __restrict__ k,
              const float* __restrict__ v,
              float* __restrict__ out)
{
    extern __shared__ float smem[];
    const int t = blockIdx.x >> 1;
    const int role = blockIdx.x & 1;
    const int h = blockIdx.y, b = blockIdx.z;
    const int tid = threadIdx.x;
    const size_t bh_base = ((size_t)(b * HH + h)) * SS * DD;
    const float* kg = k + bh_base + (size_t)t * FPT * DD;
    const float* vg = v + bh_base + (size_t)t * FPT * DD;
    const int tile = (b * HH + h) * NT + t;

    if (role == 0) {
        // ------------------------- A role -------------------------
        float* sK20 = smem + A_SK;
        float* sV20 = smem + A_SV;
        float* pK   = smem + A_PK;
        float* pV   = smem + A_PV;

        // stage same-t rows 0..19
        {
            const float4* kg4 = (const float4*)kg;
            const float4* vg4 = (const float4*)vg;
            for (int i = tid; i < IMG_START * DD / 4; i += THREADS) {
                ((float4*)sK20)[i] = kg4[i];
                ((float4*)sV20)[i] = vg4[i];
            }
        }

        const int npt = (t < WIN - 1) ? t : (WIN - 1);
        const int npk = npt * NPAST;
        const int n4  = npt * 4;

        // stage compacted past rows, JOINT-FIRST order
        {
            const int ntask = npk * 8;
            for (int r4 = tid; r4 < ntask; r4 += THREADS) {
                const int r = r4 >> 3, c = r4 & 7;
                int dt, m;
                if (r < n4) { dt = (r >> 2) + 1; m = r & 3; }
                else        { const int r2 = r - n4; dt = r2 / 15 + 1; m = 5 + r2 - (dt - 1) * 15; }
                const size_t src = bh_base + ((size_t)(t - dt) * FPT + m) * DD;
                ((float4*)pK)[r * 8 + c] = ((const float4*)(k + src))[c];
                ((float4*)pV)[r * 8 + c] = ((const float4*)(v + src))[c];
            }
        }

        __syncthreads();

        if (tid >= NIMG + IMG_START) return;   // 216 active

        const bool isImg = (tid < NIMG);
        const int qrow = isImg ? (IMG_START + tid) : (tid - NIMG);
        const bool joint = !isImg && (qrow >= JOINT_START);
        const int nk = IMG_START + (joint ? n4 : npk);

        u64 q2[16];
        loadQ(q + bh_base + ((size_t)t * FPT + qrow) * DD, q2);

        u64 acc[16];
        #pragma unroll
        for (int i = 0; i < 16; i++) acc[i] = 0ull;
        float lsum = 0.0f;

        const float* pKb = pK - IMG_START * DD;
        const float* pVb = pV - IMG_START * DD;
        #pragma unroll 2
        for (int idx = 0; idx < nk; idx++) {
            const float* kr = ((idx < IMG_START) ? sK20 : pKb) + idx * DD;
            const float* vr = ((idx < IMG_START) ? sV20 : pVb) + idx * DD;
            keyStep(q2, acc, lsum, kr, vr);
        }

        if (isImg) {
            const float inv = 1.0f / lsum;
            float4* og4 = (float4*)(out + bh_base + ((size_t)t * FPT + qrow) * DD);
            #pragma unroll
            for (int i = 0; i < 8; i++) {
                float a0, a1, a2, a3;
                unpack2(acc[2 * i], a0, a1);
                unpack2(acc[2 * i + 1], a2, a3);
                float4 o; o.x = a0 * inv; o.y = a1 * inv; o.z = a2 * inv; o.w = a3 * inv;
                og4[i] = o;
            }
        } else {
            float* pp = g_scr1 + (size_t)(tile * 20 + qrow) * SCR_STRIDE;
            #pragma unroll
            for (int i = 0; i < 16; i++) {
                float lo, hi; unpack2(acc[i], lo, hi);
                pp[2 * i] = lo; pp[2 * i + 1] = hi;
            }
            pp[32] = lsum;
        }
    } else {
        // ------------------------- B role -------------------------
        float* sK = smem + B_SK;
        float* sV = smem + B_SV;
        const float* kgi = kg + (size_t)IMG_START * DD;
        const float* vgi = vg + (size_t)IMG_START * DD;

        // stage img K/V rows (196 rows x 8 float4, pitch 36 floats)
        for (int i = tid; i < NIMG * 8; i += THREADS) {
            const int r = i >> 3, c = i & 7;
            float4 kk = ((const float4*)(kgi + (size_t)r * DD))[c];
            float4 vv = ((const float4*)(vgi + (size_t)r * DD))[c];
            *(float4*)(sK + r * B_PITCH + c * 4) = kk;
            *(float4*)(sV + r * B_PITCH + c * 4) = vv;
        }
        __syncthreads();

        const int warp = tid >> 5;    // 0..6
        const int lane = tid & 31;
        const u64 one2 = pack2(1.0f, 1.0f);

        #pragma unroll
        for (int pass = 0; pass < 3; pass++) {
            const int wq = warp + pass * 7;   // 0..20
            if (wq >= 20) break;              // warp-uniform

            u64 q2[16];
            loadQ(q + bh_base + ((size_t)t * FPT + wq) * DD, q2);

            u64 acc[16];
            #pragma unroll
            for (int i = 0; i < 16; i++) acc[i] = 0ull;
            float lsum = 0.0f;

            for (int idx = lane; idx < NIMG; idx += 32)
                keyStep(q2, acc, lsum, sK + idx * B_PITCH, sV + idx * B_PITCH);

            #pragma unroll
            for (int off = 16; off >= 1; off >>= 1) {
                lsum += __shfl_xor_sync(0xFFFFFFFFu, lsum, off);
                #pragma unroll
                for (int i = 0; i < 16; i++) {
                    u64 other = __shfl_xor_sync(0xFFFFFFFFu, acc[i], off);
                    acc[i] = fma2(other, one2, acc[i]);
                }
            }

            // raw partial -> scr2 (no merge here)
            float* pp = g_scr2 + (size_t)(tile * 20 + wq) * SCR_STRIDE;
            if (lane < 8) {
                float a0, a1, a2, a3;
                unpack2(acc[2 * lane], a0, a1);
                unpack2(acc[2 * lane + 1], a2, a3);
                float4 o; o.x = a0; o.y = a1; o.z = a2; o.w = a3;
                ((float4*)pp)[lane] = o;
            }
            if (lane == 0) pp[32] = lsum;
        }
    }
}

// ============================================================================
// Kernel C: merge scr1 + scr2 for head queries 0..19, normalize, write out.
// 384 blocks x 160 threads (20 queries x 8 lanes).  ~3us.
// ============================================================================
__global__ void eye_merge(float* __restrict__ out)
{
    const int t = blockIdx.x, h = blockIdx.y, b = blockIdx.z;
    const int tid = threadIdx.x;
    const int qi = tid >> 3;      // 0..19
    const int c  = tid & 7;       // float4 slot
    const int tile = (b * HH + h) * NT + t;
    const size_t bh_base = ((size_t)(b * HH + h)) * SS * DD;

    const float* p1 = g_scr1 + (size_t)(tile * 20 + qi) * SCR_STRIDE;
    const float* p2 = g_scr2 + (size_t)(tile * 20 + qi) * SCR_STRIDE;
    const float lt = p1[32] + p2[32];
    const float inv = 1.0f / lt;
    float4 a = ((const float4*)p1)[c];
    float4 d = ((const float4*)p2)[c];
    float4 o;
    o.x = (a.x + d.x) * inv; o.y = (a.y + d.y) * inv;
    o.z = (a.z + d.z) * inv; o.w = (a.w + d.w) * inv;
    ((float4*)(out + bh_base + ((size_t)t * FPT + qi) * DD))[c] = o;
}

extern "C" void kernel_launch(void* const* d_in, const int* in_sizes, int n_in,
                              void* d_out, int out_size)
{
    const float* q = (const float*)d_in[0];
    const float* k = (const float*)d_in[1];
    const float* v = (const float*)d_in[2];
    float* out = (float*)d_out;

    cudaFuncSetAttribute(eye_attn_main,
                         cudaFuncAttributeMaxDynamicSharedMemorySize, SMEM_BYTES);

    dim3 grid(2 * NT, HH, BB);   // (32, 12, 2): parity-interleaved roles
    eye_attn_main<<<grid, THREADS, SMEM_BYTES>>>(q, k, v, out);
    dim3 mgrid(NT, HH, BB);
    eye_merge<<<mgrid, 160>>>(out);
}

// round 15
// speedup vs baseline: 1.2478x; 1.2478x over previous
#include <cuda_runtime.h>
#include <cuda_bf16.h>
#include <math.h>

typedef unsigned long long u64;

// Problem constants (fixed by the dataset)
#define BB 2
#define HH 12
#define SS 3456
#define DD 32
#define FPT 216           // feats per timestep
#define NT (SS / FPT)     // 16 timesteps
#define WIN 8
#define IMG_START 20      // FPT - img_feat_size(196)
#define JOINT_START 4     // IMG_START - act_size(16)
#define NPAST 19          // valid past kv_m: {0,1,2,3,5..19}
#define MAXPAST ((WIN - 1) * NPAST)   // 133
#define NIMG (FPT - IMG_START)        // 196

// scale * log2(e): ex2.approx(dot) == exp(dot/sqrt(32))
#define SCL2E (0.17677669529663689f * 1.4426950408889634f)

__device__ __forceinline__ u64 fma2(u64 a, u64 b, u64 c) {
    u64 d; asm("fma.rn.f32x2 %0, %1, %2, %3;" : "=l"(d) : "l"(a), "l"(b), "l"(c)); return d;
}
__device__ __forceinline__ u64 pack2(float lo, float hi) {
    u64 d; asm("mov.b64 %0, {%1, %2};" : "=l"(d) : "f"(lo), "f"(hi)); return d;
}
__device__ __forceinline__ void unpack2(u64 a, float& lo, float& hi) {
    asm("mov.b64 {%0, %1}, %2;" : "=f"(lo), "=f"(hi) : "l"(a));
}
__device__ __forceinline__ float ex2(float x) {
    float r; asm("ex2.approx.f32 %0, %1;" : "=f"(r) : "f"(x)); return r;
}

// one key step: dot(q,k) via f32x2, exp (optionally masked), accumulate p*v.
__device__ __forceinline__ void keyStepP(const u64* __restrict__ q2, u64* __restrict__ acc,
                                         float& lsum, const float* krow, const float* vrow,
                                         bool valid)
{
    const ulonglong2* k2 = (const ulonglong2*)krow;
    u64 sA = 0ull, sB = 0ull, sC = 0ull, sD = 0ull;
    ulonglong2 kk;
    kk = k2[0]; sA = fma2(q2[0],  kk.x, sA); sB = fma2(q2[1],  kk.y, sB);
    kk = k2[1]; sC = fma2(q2[2],  kk.x, sC); sD = fma2(q2[3],  kk.y, sD);
    kk = k2[2]; sA = fma2(q2[4],  kk.x, sA); sB = fma2(q2[5],  kk.y, sB);
    kk = k2[3]; sC = fma2(q2[6],  kk.x, sC); sD = fma2(q2[7],  kk.y, sD);
    kk = k2[4]; sA = fma2(q2[8],  kk.x, sA); sB = fma2(q2[9],  kk.y, sB);
    kk = k2[5]; sC = fma2(q2[10], kk.x, sC); sD = fma2(q2[11], kk.y, sD);
    kk = k2[6]; sA = fma2(q2[12], kk.x, sA); sB = fma2(q2[13], kk.y, sB);
    kk = k2[7]; sC = fma2(q2[14], kk.x, sC); sD = fma2(q2[15], kk.y, sD);
    const u64 one2 = pack2(1.0f, 1.0f);
    u64 sAB = fma2(sA, one2, sB);
    u64 sCD = fma2(sC, one2, sD);
    u64 sT  = fma2(sAB, one2, sCD);
    float lo, hi; unpack2(sT, lo, hi);
    float p = valid ? ex2(lo + hi) : 0.0f;
    lsum += p;
    const u64 p2 = pack2(p, p);
    const ulonglong2* v2 = (const ulonglong2*)vrow;
    ulonglong2 vv;
    vv = v2[0]; acc[0]  = fma2(p2, vv.x, acc[0]);  acc[1]  = fma2(p2, vv.y, acc[1]);
    vv = v2[1]; acc[2]  = fma2(p2, vv.x, acc[2]);  acc[3]  = fma2(p2, vv.y, acc[3]);
    vv = v2[2]; acc[4]  = fma2(p2, vv.x, acc[4]);  acc[5]  = fma2(p2, vv.y, acc[5]);
    vv = v2[3]; acc[6]  = fma2(p2, vv.x, acc[6]);  acc[7]  = fma2(p2, vv.y, acc[7]);
    vv = v2[4]; acc[8]  = fma2(p2, vv.x, acc[8]);  acc[9]  = fma2(p2, vv.y, acc[9]);
    vv = v2[5]; acc[10] = fma2(p2, vv.x, acc[10]); acc[11] = fma2(p2, vv.y, acc[11]);
    vv = v2[6]; acc[12] = fma2(p2, vv.x, acc[12]); acc[13] = fma2(p2, vv.y, acc[13]);
    vv = v2[7]; acc[14] = fma2(p2, vv.x, acc[14]); acc[15] = fma2(p2, vv.y, acc[15]);
}

__device__ __forceinline__ void loadQ(const float* qrowp, u64* q2)
{
    const float4* qg4 = (const float4*)qrowp;
    #pragma unroll
    for (int i = 0; i < 8; i++) {
        float4 x = qg4[i];
        q2[2 * i]     = pack2(x.x * SCL2E, x.y * SCL2E);
        q2[2 * i + 1] = pack2(x.z * SCL2E, x.w * SCL2E);
    }
}

// ============================================================================
// Kernel A: img queries 20..215 (CLEAN R8 version, measured ~62us).
// Keys = same-t rows 0..19 + ALL past rows; 39KB tile -> 3 blocks/SM.
// Warp-uniform broadcast smem reads.
// ============================================================================
#define A_THREADS 224
#define A_SK 0
#define A_SV (IMG_START * DD)                       // 640
#define A_PK (2 * IMG_START * DD)                   // 1280
#define A_PV (2 * IMG_START * DD + MAXPAST * DD)    // 5536
#define A_SMEM_BYTES ((2 * IMG_START * DD + 2 * MAXPAST * DD) * 4)  // 39168

__global__ void __launch_bounds__(A_THREADS, 3)
eye_attn_img(const float* __restrict__ q,
             const float* __restrict__ k,
             const float* __restrict__ v,
             float* __restrict__ out)
{
    extern __shared__ float smem[];
    float* sK20 = smem + A_SK;
    float* sV20 = smem + A_SV;
    float* pK   = smem + A_PK;
    float* pV   = smem + A_PV;

    const int t = blockIdx.x, h = blockIdx.y, b = blockIdx.z;
    const int tid = threadIdx.x;
    const size_t bh_base = ((size_t)(b * HH + h)) * SS * DD;
    const float* kg = k + bh_base + (size_t)t * FPT * DD;
    const float* vg = v + bh_base + (size_t)t * FPT * DD;

    // stage same-t rows 0..19 (160 float4 each)
    {
        const float4* kg4 = (const float4*)kg;
        const float4* vg4 = (const float4*)vg;
        for (int i = tid; i < IMG_START * DD / 4; i += A_THREADS) {
            ((float4*)sK20)[i] = kg4[i];
            ((float4*)sV20)[i] = vg4[i];
        }
    }

    const int npt = (t < WIN - 1) ? t : (WIN - 1);
    const int npk = npt * NPAST;

    // stage compacted past rows (dt-major order)
    {
        const int ntask = npk * 8;
        for (int r4 = tid; r4 < ntask; r4 += A_THREADS) {
            const int r = r4 >> 3, c = r4 & 7;
            const int dt = r / NPAST + 1;
            const int i  = r - (dt - 1) * NPAST;
            const int m  = (i < 4) ? i : (i + 1);
            const size_t src = bh_base + ((size_t)(t - dt) * FPT + m) * DD;
            ((float4*)pK)[r * 8 + c] = ((const float4*)(k + src))[c];
            ((float4*)pV)[r * 8 + c] = ((const float4*)(v + src))[c];
        }
    }

    __syncthreads();

    if (tid >= NIMG) return;   // 196 active

    const int qrow = IMG_START + tid;
    u64 q2[16];
    loadQ(q + bh_base + ((size_t)t * FPT + qrow) * DD, q2);

    u64 acc[16];
    #pragma unroll
    for (int i = 0; i < 16; i++) acc[i] = 0ull;
    float lsum = 0.0f;

    // unified key list: idx<20 -> same-t row idx; else past row idx-20
    const float* pKb = pK - IMG_START * DD;
    const float* pVb = pV - IMG_START * DD;
    const int nk = IMG_START + npk;
    #pragma unroll 2
    for (int idx = 0; idx < nk; idx++) {
        const float* kr = ((idx < IMG_START) ? sK20 : pKb) + idx * DD;
        const float* vr = ((idx < IMG_START) ? sV20 : pVb) + idx * DD;
        keyStepP(q2, acc, lsum, kr, vr, true);
    }

    const float inv = 1.0f / lsum;
    float4* og4 = (float4*)(out + bh_base + ((size_t)t * FPT + qrow) * DD);
    #pragma unroll
    for (int i = 0; i < 8; i++) {
        float a0, a1, a2, a3;
        unpack2(acc[2 * i], a0, a1);
        unpack2(acc[2 * i + 1], a2, a3);
        float4 o; o.x = a0 * inv; o.y = a1 * inv; o.z = a2 * inv; o.w = a3 * inv;
        og4[i] = o;
    }
}

// ============================================================================
// Kernel B: head queries 0..19, ALL their keys, BROADCAST layout:
//   warp = key-slice (7 warps cover nk = 216 + npk keys, ~50 each),
//   lane = query (lanes 0..19 active; 20..31 duplicate q19, discarded).
// Every lane reads the SAME smem key row -> 1-phase broadcast LDS: smem
// traffic ~90KB/block instead of the ~2MB of lane-per-key variants (the
// measured 35us floor).  Joint masking: per-lane predicate over the
// JOINT-FIRST past layout.  7 warp-partials -> smem -> combine.
// Tile 87.3KB + partials 20.2KB = 107.5KB -> 2 blocks/SM.
// ============================================================================
#define B_THREADS 224     // 7 warps
#define B_NROWS (FPT + MAXPAST)                     // 349
#define B_SK 0
#define B_SV (B_NROWS * DD)                         // 11168
#define B_PART (2 * B_NROWS * DD)                   // 22336 (floats)
#define B_PSTRIDE 36                                // floats per (warp,query) slot
#define B_SMEM_BYTES ((B_PART + 7 * 20 * B_PSTRIDE) * 4)   // 109504

__global__ void __launch_bounds__(B_THREADS, 2)
eye_attn_head(const float* __restrict__ q,
              const float* __restrict__ k,
              const float* __restrict__ v,
              float* __restrict__ out)
{
    extern __shared__ float smem[];
    float* sK   = smem + B_SK;    // rows 0..215 same-t; 216.. past (joint-first)
    float* sV   = smem + B_SV;
    float* part = smem + B_PART;

    const int t = blockIdx.x, h = blockIdx.y, b = blockIdx.z;
    const int tid = threadIdx.x;
    const size_t bh_base = ((size_t)(b * HH + h)) * SS * DD;
    const float* kg = k + bh_base + (size_t)t * FPT * DD;
    const float* vg = v + bh_base + (size_t)t * FPT * DD;

    const int npt = (t < WIN - 1) ? t : (WIN - 1);
    const int npk = npt * NPAST;
    const int n4  = npt * 4;

    // stage same-t rows 0..215 (1728 float4 each of K and V; coalesced)
    for (int i = tid; i < FPT * 8; i += B_THREADS) {
        ((float4*)sK)[i] = ((const float4*)kg)[i];
        ((float4*)sV)[i] = ((const float4*)vg)[i];
    }
    // stage past rows JOINT-FIRST at rows 216..: [0,n4): m in {0..3}; [n4,npk): m in {5..19}
    {
        const int ntask = npk * 8;
        for (int i = tid; i < ntask; i += B_THREADS) {
            const int r = i >> 3, c = i & 7;
            int dt, m;
            if (r < n4) { dt = (r >> 2) + 1; m = r & 3; }
            else        { const int r2 = r - n4; dt = r2 / 15 + 1; m = 5 + r2 - (dt - 1) * 15; }
            const size_t src = bh_base + ((size_t)(t - dt) * FPT + m) * DD;
            ((float4*)sK)[(FPT + r) * 8 + c] = ((const float4*)(k + src))[c];
            ((float4*)sV)[(FPT + r) * 8 + c] = ((const float4*)(v + src))[c];
        }
    }
    __syncthreads();

    const int warp = tid >> 5;    // 0..6 : key-slice
    const int lane = tid & 31;
    const int qi   = (lane < 20) ? lane : 19;   // lane = query (dups discarded)

    const int nk = FPT + npk;
    const int cs = (nk + 6) / 7;
    const int s0 = warp * cs;
    const int s1 = (s0 + cs < nk) ? (s0 + cs) : nk;

    // valid(q, idx): same-t always; past rows beyond n4 only for head q<4
    const int vbound = FPT + n4;
    const bool headq = (qi < JOINT_START);

    u64 q2[16];
    loadQ(q + bh_base + ((size_t)t * FPT + qi) * DD, q2);

    u64 acc[16];
    #pragma unroll
    for (int i = 0; i < 16; i++) acc[i] = 0ull;
    float lsum = 0.0f;

    #pragma unroll 2
    for (int idx = s0; idx < s1; idx++) {
        const bool valid = headq | (idx < vbound);
        keyStepP(q2, acc, lsum, sK + idx * DD, sV + idx * DD, valid);
    }

    // publish per-(warp, query) partials
    if (lane < 20) {
        float* pp = part + (warp * 20 + qi) * B_PSTRIDE;
        #pragma unroll
        for (int i = 0; i < 16; i++) {
            float lo, hi; unpack2(acc[i], lo, hi);
            pp[2 * i] = lo; pp[2 * i + 1] = hi;
        }
        pp[32] = lsum;
    }

    __syncthreads();

    // combine: 160 threads = 20 queries x 8 float4-slots
    if (tid < 160) {
        const int qo = tid >> 3;
        const int c  = tid & 7;
        float4 a = make_float4(0.f, 0.f, 0.f, 0.f);
        float lt = 0.f;
        #pragma unroll
        for (int w = 0; w < 7; w++) {
            const float* pp = part + (w * 20 + qo) * B_PSTRIDE;
            float4 x = ((const float4*)pp)[c];
            a.x += x.x; a.y += x.y; a.z += x.z; a.w += x.w;
            lt += pp[32];
        }
        const float inv = 1.0f / lt;
        float4 o; o.x = a.x * inv; o.y = a.y * inv; o.z = a.z * inv; o.w = a.w * inv;
        ((float4*)(out + bh_base + ((size_t)t * FPT + qo) * DD))[c] = o;
    }
}

extern "C" void kernel_launch(void* const* d_in, const int* in_sizes, int n_in,
                              void* d_out, int out_size)
{
    const float* q = (const float*)d_in[0];
    const float* k = (const float*)d_in[1];
    const float* v = (const float*)d_in[2];
    float* out = (float*)d_out;

    cudaFuncSetAttribute(eye_attn_img,
                         cudaFuncAttributeMaxDynamicSharedMemorySize, A_SMEM_BYTES);
    cudaFuncSetAttribute(eye_attn_head,
                         cudaFuncAttributeMaxDynamicSharedMemorySize, B_SMEM_BYTES);

    dim3 grid(NT, HH, BB);   // (16, 12, 2)
    eye_attn_img<<<grid, A_THREADS, A_SMEM_BYTES>>>(q, k, v, out);
    eye_attn_head<<<grid, B_THREADS, B_SMEM_BYTES>>>(q, k, v, out);
}